// round 8
// baseline (speedup 1.0000x reference)
#include <cuda_runtime.h>
#include <cuda_bf16.h>
#include <cstdint>

#define LVL  7
#define W0S  56.0f
#define NT   512

// SMEM byte offsets
#define SOFF_XH   0
#define SOFF_XL   32768
#define SOFF_WMH  65536
#define SOFF_WML  98304
#define SOFF_WHH  131072
#define SOFF_WHL  163840
#define SOFF_GXS  196608   // 1792 floats
#define SOFF_BMS  203776   // 896 floats
#define SOFF_BHS  207360   // 896 floats
#define SOFF_ASM  210944   // 1792 floats
#define SMEM_TOTAL 218112

// Pre-split, pre-swizzled bf16 weight tiles (n-major: W[n][k]).
__device__ __align__(16) char g_Wmh[LVL * 32768];
__device__ __align__(16) char g_Wml[LVL * 32768];
__device__ __align__(16) char g_Whh[LVL * 32768];
__device__ __align__(16) char g_Whl[LVL * 32768];
__device__ float g_As[LVL * 256];

__host__ __device__ __forceinline__ int swoff(int r, int k) {
    return (r << 8) + ((((k >> 3) ^ (r & 7)) & 15) << 4) + ((k & 7) << 1);
}

__global__ void prep_kernel(const float* __restrict__ Wm,
                            const float* __restrict__ Wh,
                            const float* __restrict__ A,
                            const float* __restrict__ sigma) {
    int i0 = blockIdx.x * blockDim.x + threadIdx.x;
    int stride = gridDim.x * blockDim.x;
    for (int idx = i0; idx < LVL * 16384; idx += stride) {
        int l = idx >> 14, rem = idx & 16383;
        int n = rem >> 7, k = rem & 127;
        int dst = l * 32768 + swoff(n, k);
        float wm = Wm[idx];
        __nv_bfloat16 hm = __float2bfloat16(wm);
        *(__nv_bfloat16*)(g_Wmh + dst) = hm;
        *(__nv_bfloat16*)(g_Wml + dst) = __float2bfloat16(wm - __bfloat162float(hm));
        float wh = Wh[idx];
        __nv_bfloat16 hh = __float2bfloat16(wh);
        *(__nv_bfloat16*)(g_Whh + dst) = hh;
        *(__nv_bfloat16*)(g_Whl + dst) = __float2bfloat16(wh - __bfloat162float(hh));
    }
    for (int idx = i0; idx < LVL * 256; idx += stride) {
        int l = idx >> 8;
        g_As[idx] = A[idx] * (6.28318530717958647692f * sigma[l]);
    }
}

__device__ __forceinline__ uint32_t smem_u32(const void* p) {
    uint32_t a;
    asm("{ .reg .u64 t; cvta.to.shared.u64 t, %1; cvt.u32.u64 %0, t; }" : "=r"(a) : "l"(p));
    return a;
}

__device__ __forceinline__ void cp16(uint32_t dst, const void* src) {
    asm volatile("cp.async.cg.shared.global [%0], [%1], 16;" :: "r"(dst), "l"(src));
}
#define CP_COMMIT() asm volatile("cp.async.commit_group;" ::: "memory")
#define CP_WAIT(N)  asm volatile("cp.async.wait_group %0;" :: "n"(N) : "memory")

__device__ __forceinline__ void ldsm4(uint32_t* r, uint32_t addr) {
    asm volatile("ldmatrix.sync.aligned.m8n8.x4.shared.b16 {%0,%1,%2,%3}, [%4];"
                 : "=r"(r[0]), "=r"(r[1]), "=r"(r[2]), "=r"(r[3]) : "r"(addr));
}

__device__ __forceinline__ void mma16816(float* d, const uint32_t* a, const uint32_t* b) {
    asm volatile(
        "mma.sync.aligned.m16n8k16.row.col.f32.bf16.bf16.f32 "
        "{%0,%1,%2,%3}, {%4,%5,%6,%7}, {%8,%9}, {%0,%1,%2,%3};"
        : "+f"(d[0]), "+f"(d[1]), "+f"(d[2]), "+f"(d[3])
        : "r"(a[0]), "r"(a[1]), "r"(a[2]), "r"(a[3]), "r"(b[0]), "r"(b[1]));
}

__device__ __forceinline__ uint32_t addrA(uint32_t base, int lane, int r0, int k0) {
    int sub = lane >> 3;
    int row = r0 + (lane & 7) + ((sub & 1) << 3);
    int kk  = k0 + ((sub & 2) << 2);
    return base + (row << 8) + ((((kk >> 3) ^ (row & 7)) & 15) << 4);
}

__device__ __forceinline__ uint32_t addrB(uint32_t base, int lane, int n0, int k0) {
    int sub = lane >> 3;
    int row = n0 + (lane & 7) + ((sub & 2) << 2);
    int kk  = k0 + ((sub & 1) << 3);
    return base + (row << 8) + ((((kk >> 3) ^ (row & 7)) & 15) << 4);
}

// One 32x32 warp-tile, 3-chain split, single weight slot.
__device__ __forceinline__ void gemm_split3(uint32_t sb, int lane, int wm, int wn,
                                            uint32_t offWh, uint32_t offWl,
                                            float acc[2][4][4]) {
#pragma unroll 1
    for (int k0 = 0; k0 < 128; k0 += 16) {
        uint32_t ah[2][4], al[2][4], bh[2][4], bl[2][4];
#pragma unroll
        for (int mt = 0; mt < 2; ++mt) {
            int r0 = wm * 32 + mt * 16;
            ldsm4(ah[mt], addrA(sb + SOFF_XH, lane, r0, k0));
            ldsm4(al[mt], addrA(sb + SOFF_XL, lane, r0, k0));
        }
#pragma unroll
        for (int nb = 0; nb < 2; ++nb) {
            int n0 = wn * 32 + nb * 16;
            ldsm4(bh[nb], addrB(sb + offWh, lane, n0, k0));
            ldsm4(bl[nb], addrB(sb + offWl, lane, n0, k0));
        }
#pragma unroll
        for (int mt = 0; mt < 2; ++mt)
#pragma unroll
            for (int nt = 0; nt < 4; ++nt) {
                const uint32_t* bph = &bh[nt >> 1][(nt & 1) << 1];
                const uint32_t* bpl = &bl[nt >> 1][(nt & 1) << 1];
                mma16816(acc[mt][nt], ah[mt], bph);
                mma16816(acc[mt][nt], ah[mt], bpl);
                mma16816(acc[mt][nt], al[mt], bph);
            }
    }
}

// Fused: high(ly) into accA (Wh slot) and mid(ly+1) into accB (Wm slot),
// sharing the x-side fragments.
__device__ __forceinline__ void gemm_fused(uint32_t sb, int lane, int wm, int wn,
                                           float accA[2][4][4], float accB[2][4][4]) {
#pragma unroll 1
    for (int k0 = 0; k0 < 128; k0 += 16) {
        uint32_t ah[2][4], al[2][4];
#pragma unroll
        for (int mt = 0; mt < 2; ++mt) {
            int r0 = wm * 32 + mt * 16;
            ldsm4(ah[mt], addrA(sb + SOFF_XH, lane, r0, k0));
            ldsm4(al[mt], addrA(sb + SOFF_XL, lane, r0, k0));
        }
        {
            uint32_t bh[2][4], bl[2][4];
#pragma unroll
            for (int nb = 0; nb < 2; ++nb) {
                int n0 = wn * 32 + nb * 16;
                ldsm4(bh[nb], addrB(sb + SOFF_WHH, lane, n0, k0));
                ldsm4(bl[nb], addrB(sb + SOFF_WHL, lane, n0, k0));
            }
#pragma unroll
            for (int mt = 0; mt < 2; ++mt)
#pragma unroll
                for (int nt = 0; nt < 4; ++nt) {
                    const uint32_t* bph = &bh[nt >> 1][(nt & 1) << 1];
                    const uint32_t* bpl = &bl[nt >> 1][(nt & 1) << 1];
                    mma16816(accA[mt][nt], ah[mt], bph);
                    mma16816(accA[mt][nt], ah[mt], bpl);
                    mma16816(accA[mt][nt], al[mt], bph);
                }
        }
        {
            uint32_t bh[2][4], bl[2][4];
#pragma unroll
            for (int nb = 0; nb < 2; ++nb) {
                int n0 = wn * 32 + nb * 16;
                ldsm4(bh[nb], addrB(sb + SOFF_WMH, lane, n0, k0));
                ldsm4(bl[nb], addrB(sb + SOFF_WML, lane, n0, k0));
            }
#pragma unroll
            for (int mt = 0; mt < 2; ++mt)
#pragma unroll
                for (int nt = 0; nt < 4; ++nt) {
                    const uint32_t* bph = &bh[nt >> 1][(nt & 1) << 1];
                    const uint32_t* bpl = &bl[nt >> 1][(nt & 1) << 1];
                    mma16816(accB[mt][nt], ah[mt], bph);
                    mma16816(accB[mt][nt], ah[mt], bpl);
                    mma16816(accB[mt][nt], al[mt], bph);
                }
        }
    }
}

__device__ __forceinline__ void zero_acc(float a[2][4][4]) {
#pragma unroll
    for (int i = 0; i < 2; ++i)
#pragma unroll
        for (int j = 0; j < 4; ++j)
#pragma unroll
            for (int k = 0; k < 4; ++k) a[i][j][k] = 0.0f;
}

__device__ __forceinline__ void split_store(char* smem, int r, int c0, float va, float vb) {
    __nv_bfloat16 ha = __float2bfloat16(va), hb = __float2bfloat16(vb);
    float la = va - __bfloat162float(ha);
    float lb = vb - __bfloat162float(hb);
    uint32_t hi32 = ((uint32_t)__bfloat16_as_ushort(hb) << 16) | (uint32_t)__bfloat16_as_ushort(ha);
    uint32_t lo32 = ((uint32_t)__bfloat16_as_ushort(__float2bfloat16(lb)) << 16) |
                    (uint32_t)__bfloat16_as_ushort(__float2bfloat16(la));
    int off = swoff(r, c0);
    *(uint32_t*)(smem + SOFF_XH + off) = hi32;
    *(uint32_t*)(smem + SOFF_XL + off) = lo32;
}

__device__ __forceinline__ void prefetch_slot(uint32_t sb, int tid, int ly,
                                              uint32_t soff_hi, uint32_t soff_lo,
                                              const char* ghi, const char* glo) {
    const char* srch = ghi + ly * 32768;
    const char* srcl = glo + ly * 32768;
#pragma unroll
    for (int t = 0; t < 4; ++t) {
        int b = (tid + t * NT) * 16;
        cp16(sb + soff_hi + b, srch + b);
        cp16(sb + soff_lo + b, srcl + b);
    }
}

// mid epilogue for layer ly: x(ly+1) = sin(56*(d+bm)) + sin(g.A) -> x tiles
__device__ __forceinline__ void mid_epi(char* smem, float acc[2][4][4], int ly,
                                        int wm, int wn, int qr, int qc) {
    float* gxs = (float*)(smem + SOFF_GXS);
    float* bms = (float*)(smem + SOFF_BMS);
    float* Asm = (float*)(smem + SOFF_ASM);
#pragma unroll
    for (int mt = 0; mt < 2; ++mt)
#pragma unroll
        for (int h = 0; h < 2; ++h) {
            int r = wm * 32 + mt * 16 + qr + (h << 3);
            float g0 = gxs[r * 14 + 2 * ly];
            float g1 = gxs[r * 14 + 2 * ly + 1];
#pragma unroll
            for (int nt = 0; nt < 4; ++nt) {
                int c0 = wn * 32 + nt * 8 + 2 * qc;
                float da = acc[mt][nt][2 * h];
                float db = acc[mt][nt][2 * h + 1];
                float va = __sinf(W0S * (da + bms[ly * 128 + c0])) +
                           __sinf(g0 * Asm[ly * 256 + c0] + g1 * Asm[ly * 256 + 128 + c0]);
                float vb = __sinf(W0S * (db + bms[ly * 128 + c0 + 1])) +
                           __sinf(g0 * Asm[ly * 256 + c0 + 1] + g1 * Asm[ly * 256 + 129 + c0]);
                split_store(smem, r, c0, va, vb);
            }
        }
}

// high epilogue for layer ly: out (+)= sin(56*(d+bh)) * (1/7)
template <bool FIRST>
__device__ __forceinline__ void high_epi(char* smem, float acc[2][4][4], int ly,
                                         float* __restrict__ out, int p0,
                                         int wm, int wn, int qr, int qc) {
    float* bhs = (float*)(smem + SOFF_BHS);
    const float inv7 = 1.0f / 7.0f;
#pragma unroll
    for (int mt = 0; mt < 2; ++mt)
#pragma unroll
        for (int h = 0; h < 2; ++h) {
            int r = wm * 32 + mt * 16 + qr + (h << 3);
            size_t base = (size_t)(p0 + r) * 131 + 3;
#pragma unroll
            for (int nt = 0; nt < 4; ++nt) {
                int c0 = wn * 32 + nt * 8 + 2 * qc;
                float sa = __sinf(W0S * (acc[mt][nt][2 * h]     + bhs[ly * 128 + c0]))     * inv7;
                float sb = __sinf(W0S * (acc[mt][nt][2 * h + 1] + bhs[ly * 128 + c0 + 1])) * inv7;
                if (FIRST) {
                    out[base + c0]     = sa;
                    out[base + c0 + 1] = sb;
                } else {
                    out[base + c0]     += sa;
                    out[base + c0 + 1] += sb;
                }
            }
        }
}

__global__ void __launch_bounds__(NT, 1) ffb_main(
    const float* __restrict__ in_pos,
    const float* __restrict__ gfeat,
    const float* __restrict__ W0,
    const float* __restrict__ b0,
    const float* __restrict__ b_mid,
    const float* __restrict__ b_high,
    float* __restrict__ out) {
    extern __shared__ char smem[];
    const uint32_t sb = smem_u32(smem);
    const int tid = threadIdx.x, wid = tid >> 5, lane = tid & 31;
    const int wm = wid & 3, wn = wid >> 2;      // 4 x 4 warp grid
    const int qr = lane >> 2, qc = lane & 3;
    const int p0 = blockIdx.x << 7;

    float* gxs = (float*)(smem + SOFF_GXS);
    float* bms = (float*)(smem + SOFF_BMS);
    float* bhs = (float*)(smem + SOFF_BHS);
    float* Asm = (float*)(smem + SOFF_ASM);

    // Kick off layer-0 weight prefetch (groups: Gm0, Gh0).
    prefetch_slot(sb, tid, 0, SOFF_WMH, SOFF_WML, g_Wmh, g_Wml);
    CP_COMMIT();
    prefetch_slot(sb, tid, 0, SOFF_WHH, SOFF_WHL, g_Whh, g_Whl);
    CP_COMMIT();

    // Stage per-CTA grid feats / biases / A (overlaps with cp.async)
    for (int idx = tid; idx < 1792; idx += NT) {
        int m = idx / 14, c = idx - m * 14;
        gxs[idx] = gfeat[(size_t)(p0 + m) * 17 + 3 + c];
        Asm[idx] = g_As[idx];
    }
    for (int idx = tid; idx < 896; idx += NT) {
        bms[idx] = b_mid[idx];
        bhs[idx] = b_high[idx];
    }

    // pos01 outputs
    if (tid < 128) {
        size_t m = p0 + tid;
        float a = in_pos[m * 3 + 0], b = in_pos[m * 3 + 1], c = in_pos[m * 3 + 2];
        out[m * 131 + 0] = (a + 1.0f) * 0.5f;
        out[m * 131 + 1] = (b + 1.0f) * 0.5f;
        out[m * 131 + 2] = (c + 1.0f) * 0.5f;
    }

    // Layer 0: x = sin(56*(pos @ W0^T + b0)) -> split tiles
    for (int p = tid; p < 8192; p += NT) {
        int r = p >> 6, n = (p & 63) << 1;
        const float* pp = in_pos + (size_t)(p0 + r) * 3;
        float x0 = pp[0], x1 = pp[1], x2 = pp[2];
        float va = __sinf(W0S * (x0 * W0[n * 3 + 0] + x1 * W0[n * 3 + 1] + x2 * W0[n * 3 + 2] + b0[n]));
        float vb = __sinf(W0S * (x0 * W0[n * 3 + 3] + x1 * W0[n * 3 + 4] + x2 * W0[n * 3 + 5] + b0[n + 1]));
        split_store(smem, r, n, va, vb);
    }

    CP_WAIT(1);        // Wm(0) arrived
    __syncthreads();   // publish x(0), Wm(0), tables

    // ---- prologue: mid-GEMM(0) ----
    {
        float acc[2][4][4];
        zero_acc(acc);
        gemm_split3(sb, lane, wm, wn, SOFF_WMH, SOFF_WML, acc);
        __syncthreads();                 // all x(0)/Wm(0) reads done
        prefetch_slot(sb, tid, 1, SOFF_WMH, SOFF_WML, g_Wmh, g_Wml);  // Wm(1)
        CP_COMMIT();
        mid_epi(smem, acc, 0, wm, wn, qr, qc);   // writes x(1)
        CP_WAIT(0);                      // Wh(0), Wm(1) complete
        __syncthreads();                 // publish x(1) + weights
    }

    // ---- fused phases p = 0..5: high(p) || mid(p+1) ----
#pragma unroll 1
    for (int p = 0; p < LVL - 1; ++p) {
        float accA[2][4][4], accB[2][4][4];
        zero_acc(accA);
        zero_acc(accB);
        gemm_fused(sb, lane, wm, wn, accA, accB);
        __syncthreads();                 // x(p+1)/Wh(p)/Wm(p+1) reads done

        prefetch_slot(sb, tid, p + 1, SOFF_WHH, SOFF_WHL, g_Whh, g_Whl);
        CP_COMMIT();
        if (p + 2 < LVL) {
            prefetch_slot(sb, tid, p + 2, SOFF_WMH, SOFF_WML, g_Wmh, g_Wml);
            CP_COMMIT();
        }

        if (p == 0) high_epi<true >(smem, accA, p, out, p0, wm, wn, qr, qc);
        else        high_epi<false>(smem, accA, p, out, p0, wm, wn, qr, qc);
        mid_epi(smem, accB, p + 1, wm, wn, qr, qc);   // writes x(p+2)

        CP_WAIT(0);
        __syncthreads();                 // publish x(p+2) + new weights
    }

    // ---- epilogue: high(6) ----
    {
        float acc[2][4][4];
        zero_acc(acc);
        gemm_split3(sb, lane, wm, wn, SOFF_WHH, SOFF_WHL, acc);
        high_epi<false>(smem, acc, LVL - 1, out, p0, wm, wn, qr, qc);
    }
}

extern "C" void kernel_launch(void* const* d_in, const int* in_sizes, int n_in,
                              void* d_out, int out_size) {
    const float* in_pos = (const float*)d_in[0];
    const float* gfeat  = (const float*)d_in[1];
    const float* ffn_A  = (const float*)d_in[2];
    const float* sigma  = (const float*)d_in[3];
    const float* W0     = (const float*)d_in[4];
    const float* b0     = (const float*)d_in[5];
    const float* W_mid  = (const float*)d_in[6];
    const float* b_mid  = (const float*)d_in[7];
    const float* W_high = (const float*)d_in[8];
    const float* b_high = (const float*)d_in[9];
    float* out = (float*)d_out;

    int N = in_sizes[0] / 3;

    prep_kernel<<<448, 256>>>(W_mid, W_high, ffn_A, sigma);

    cudaFuncSetAttribute(ffb_main, cudaFuncAttributeMaxDynamicSharedMemorySize, SMEM_TOTAL);
    ffb_main<<<N / 128, NT, SMEM_TOTAL>>>(in_pos, gfeat, W0, b0, b_mid, b_high, out);
}

// round 10
// speedup vs baseline: 1.7500x; 1.7500x over previous
#include <cuda_runtime.h>
#include <cuda_bf16.h>
#include <cstdint>

#define LVL  7
#define W0S  56.0f
#define NT   512

// SMEM byte offsets
#define SOFF_XH   0
#define SOFF_XL   32768
#define SOFF_WMH  65536
#define SOFF_WML  98304
#define SOFF_WHH  131072
#define SOFF_WHL  163840
#define SOFF_GXS  196608   // 1792 floats
#define SOFF_BMS  203776   // 896 floats
#define SOFF_BHS  207360   // 896 floats
#define SOFF_ASM  210944   // 1792 floats
#define SMEM_TOTAL 218112

// Pre-split, pre-swizzled bf16 weight tiles (n-major: W[n][k]).
__device__ __align__(16) char g_Wmh[LVL * 32768];
__device__ __align__(16) char g_Wml[LVL * 32768];
__device__ __align__(16) char g_Whh[LVL * 32768];
__device__ __align__(16) char g_Whl[LVL * 32768];
__device__ float g_As[LVL * 256];

__host__ __device__ __forceinline__ int swoff(int r, int k) {
    return (r << 8) + ((((k >> 3) ^ (r & 7)) & 15) << 4) + ((k & 7) << 1);
}

__global__ void prep_kernel(const float* __restrict__ Wm,
                            const float* __restrict__ Wh,
                            const float* __restrict__ A,
                            const float* __restrict__ sigma) {
    int i0 = blockIdx.x * blockDim.x + threadIdx.x;
    int stride = gridDim.x * blockDim.x;
    for (int idx = i0; idx < LVL * 16384; idx += stride) {
        int l = idx >> 14, rem = idx & 16383;
        int n = rem >> 7, k = rem & 127;
        int dst = l * 32768 + swoff(n, k);
        float wm = Wm[idx];
        __nv_bfloat16 hm = __float2bfloat16(wm);
        *(__nv_bfloat16*)(g_Wmh + dst) = hm;
        *(__nv_bfloat16*)(g_Wml + dst) = __float2bfloat16(wm - __bfloat162float(hm));
        float wh = Wh[idx];
        __nv_bfloat16 hh = __float2bfloat16(wh);
        *(__nv_bfloat16*)(g_Whh + dst) = hh;
        *(__nv_bfloat16*)(g_Whl + dst) = __float2bfloat16(wh - __bfloat162float(hh));
    }
    for (int idx = i0; idx < LVL * 256; idx += stride) {
        int l = idx >> 8;
        g_As[idx] = A[idx] * (6.28318530717958647692f * sigma[l]);
    }
}

__device__ __forceinline__ uint32_t smem_u32(const void* p) {
    uint32_t a;
    asm("{ .reg .u64 t; cvta.to.shared.u64 t, %1; cvt.u32.u64 %0, t; }" : "=r"(a) : "l"(p));
    return a;
}

__device__ __forceinline__ void cp16(uint32_t dst, const void* src) {
    asm volatile("cp.async.cg.shared.global [%0], [%1], 16;" :: "r"(dst), "l"(src));
}
#define CP_COMMIT() asm volatile("cp.async.commit_group;" ::: "memory")
#define CP_WAIT(N)  asm volatile("cp.async.wait_group %0;" :: "n"(N) : "memory")

__device__ __forceinline__ void ldsm4(uint32_t* r, uint32_t addr) {
    asm volatile("ldmatrix.sync.aligned.m8n8.x4.shared.b16 {%0,%1,%2,%3}, [%4];"
                 : "=r"(r[0]), "=r"(r[1]), "=r"(r[2]), "=r"(r[3]) : "r"(addr));
}

__device__ __forceinline__ void mma16816(float* d, const uint32_t* a, const uint32_t* b) {
    asm volatile(
        "mma.sync.aligned.m16n8k16.row.col.f32.bf16.bf16.f32 "
        "{%0,%1,%2,%3}, {%4,%5,%6,%7}, {%8,%9}, {%0,%1,%2,%3};"
        : "+f"(d[0]), "+f"(d[1]), "+f"(d[2]), "+f"(d[3])
        : "r"(a[0]), "r"(a[1]), "r"(a[2]), "r"(a[3]), "r"(b[0]), "r"(b[1]));
}

__device__ __forceinline__ uint32_t addrA(uint32_t base, int lane, int r0, int k0) {
    int sub = lane >> 3;
    int row = r0 + (lane & 7) + ((sub & 1) << 3);
    int kk  = k0 + ((sub & 2) << 2);
    return base + (row << 8) + ((((kk >> 3) ^ (row & 7)) & 15) << 4);
}

__device__ __forceinline__ uint32_t addrB(uint32_t base, int lane, int n0, int k0) {
    int sub = lane >> 3;
    int row = n0 + (lane & 7) + ((sub & 2) << 2);
    int kk  = k0 + ((sub & 1) << 3);
    return base + (row << 8) + ((((kk >> 3) ^ (row & 7)) & 15) << 4);
}

// One 32x32 warp-tile, 3-chain split. K-loop start rotated by woff so warps
// de-synchronize their LDSM bursts (crossbar and tensor pipe overlap).
__device__ __forceinline__ void gemm_split3(uint32_t sb, int lane, int wm, int wn,
                                            int woff,
                                            uint32_t offWh, uint32_t offWl,
                                            float acc[2][4][4]) {
#pragma unroll 1
    for (int kk = 0; kk < 8; ++kk) {
        int k0 = ((kk + woff) & 7) << 4;
        uint32_t ah[2][4], al[2][4], bh[2][4], bl[2][4];
#pragma unroll
        for (int mt = 0; mt < 2; ++mt) {
            int r0 = wm * 32 + mt * 16;
            ldsm4(ah[mt], addrA(sb + SOFF_XH, lane, r0, k0));
            ldsm4(al[mt], addrA(sb + SOFF_XL, lane, r0, k0));
        }
#pragma unroll
        for (int nb = 0; nb < 2; ++nb) {
            int n0 = wn * 32 + nb * 16;
            ldsm4(bh[nb], addrB(sb + offWh, lane, n0, k0));
            ldsm4(bl[nb], addrB(sb + offWl, lane, n0, k0));
        }
#pragma unroll
        for (int mt = 0; mt < 2; ++mt)
#pragma unroll
            for (int nt = 0; nt < 4; ++nt) {
                const uint32_t* bph = &bh[nt >> 1][(nt & 1) << 1];
                const uint32_t* bpl = &bl[nt >> 1][(nt & 1) << 1];
                mma16816(acc[mt][nt], ah[mt], bph);
                mma16816(acc[mt][nt], ah[mt], bpl);
                mma16816(acc[mt][nt], al[mt], bph);
            }
    }
}

__device__ __forceinline__ void split_store(char* smem, int r, int c0, float va, float vb) {
    __nv_bfloat16 ha = __float2bfloat16(va), hb = __float2bfloat16(vb);
    float la = va - __bfloat162float(ha);
    float lb = vb - __bfloat162float(hb);
    uint32_t hi32 = ((uint32_t)__bfloat16_as_ushort(hb) << 16) | (uint32_t)__bfloat16_as_ushort(ha);
    uint32_t lo32 = ((uint32_t)__bfloat16_as_ushort(__float2bfloat16(lb)) << 16) |
                    (uint32_t)__bfloat16_as_ushort(__float2bfloat16(la));
    int off = swoff(r, c0);
    *(uint32_t*)(smem + SOFF_XH + off) = hi32;
    *(uint32_t*)(smem + SOFF_XL + off) = lo32;
}

__device__ __forceinline__ void prefetch_slot(uint32_t sb, int tid, int ly,
                                              uint32_t soff_hi, uint32_t soff_lo,
                                              const char* ghi, const char* glo) {
    const char* srch = ghi + ly * 32768;
    const char* srcl = glo + ly * 32768;
#pragma unroll
    for (int t = 0; t < 4; ++t) {
        int b = (tid + t * NT) * 16;
        cp16(sb + soff_hi + b, srch + b);
        cp16(sb + soff_lo + b, srcl + b);
    }
}

__global__ void __launch_bounds__(NT, 1) ffb_main(
    const float* __restrict__ in_pos,
    const float* __restrict__ gfeat,
    const float* __restrict__ W0,
    const float* __restrict__ b0,
    const float* __restrict__ b_mid,
    const float* __restrict__ b_high,
    float* __restrict__ out) {
    extern __shared__ char smem[];
    const uint32_t sb = smem_u32(smem);
    const int tid = threadIdx.x, wid = tid >> 5, lane = tid & 31;
    const int wm = wid & 3, wn = wid >> 2;      // 4 x 4 warp grid
    const int woff = wid & 7;                    // k-stagger offset
    const int qr = lane >> 2, qc = lane & 3;
    const int p0 = blockIdx.x << 7;

    float* gxs = (float*)(smem + SOFF_GXS);
    float* bms = (float*)(smem + SOFF_BMS);
    float* bhs = (float*)(smem + SOFF_BHS);
    float* Asm = (float*)(smem + SOFF_ASM);

    // Kick off layer-0 weight prefetch (two groups: Gm0, Gh0).
    prefetch_slot(sb, tid, 0, SOFF_WMH, SOFF_WML, g_Wmh, g_Wml);
    CP_COMMIT();
    prefetch_slot(sb, tid, 0, SOFF_WHH, SOFF_WHL, g_Whh, g_Whl);
    CP_COMMIT();

    // Stage per-CTA grid feats / biases / A (overlaps with cp.async)
    for (int idx = tid; idx < 1792; idx += NT) {
        int m = idx / 14, c = idx - m * 14;
        gxs[idx] = gfeat[(size_t)(p0 + m) * 17 + 3 + c];
        Asm[idx] = g_As[idx];
    }
    for (int idx = tid; idx < 896; idx += NT) {
        bms[idx] = b_mid[idx];
        bhs[idx] = b_high[idx];
    }

    // pos01 outputs
    if (tid < 128) {
        size_t m = p0 + tid;
        float a = in_pos[m * 3 + 0], b = in_pos[m * 3 + 1], c = in_pos[m * 3 + 2];
        out[m * 131 + 0] = (a + 1.0f) * 0.5f;
        out[m * 131 + 1] = (b + 1.0f) * 0.5f;
        out[m * 131 + 2] = (c + 1.0f) * 0.5f;
    }

    // Layer 0: x = sin(56*(pos @ W0^T + b0)) -> split tiles
    for (int p = tid; p < 8192; p += NT) {
        int r = p >> 6, n = (p & 63) << 1;
        const float* pp = in_pos + (size_t)(p0 + r) * 3;
        float x0 = pp[0], x1 = pp[1], x2 = pp[2];
        float va = __sinf(W0S * (x0 * W0[n * 3 + 0] + x1 * W0[n * 3 + 1] + x2 * W0[n * 3 + 2] + b0[n]));
        float vb = __sinf(W0S * (x0 * W0[n * 3 + 3] + x1 * W0[n * 3 + 4] + x2 * W0[n * 3 + 5] + b0[n + 1]));
        split_store(smem, r, n, va, vb);
    }

    float buf[2][4][4];
#pragma unroll
    for (int a = 0; a < 2; ++a)
#pragma unroll
        for (int b = 0; b < 4; ++b)
#pragma unroll
            for (int c = 0; c < 4; ++c) buf[a][b][c] = 0.0f;

    CP_WAIT(1);        // Wm(0) arrived (Wh(0) may still be in flight)
    __syncthreads();   // publish x(0), Wm(0), staged tables

#pragma unroll 1
    for (int ly = 0; ly < LVL; ++ly) {
        // ---- mid GEMM (reads x(ly), Wm slot) ----
        float acc[2][4][4];
#pragma unroll
        for (int a = 0; a < 2; ++a)
#pragma unroll
            for (int b = 0; b < 4; ++b)
#pragma unroll
                for (int c = 0; c < 4; ++c) acc[a][b][c] = 0.0f;
        gemm_split3(sb, lane, wm, wn, woff, SOFF_WMH, SOFF_WML, acc);
        __syncthreads();   // B1: x + Wm slot readers done

        if (ly < LVL - 1) {   // prefetch Wm(ly+1) into the now-free slot
            prefetch_slot(sb, tid, ly + 1, SOFF_WMH, SOFF_WML, g_Wmh, g_Wml);
            CP_COMMIT();
        }

        // ---- mid epilogue: x' = sin(56*(d+bm)) + sin(g.A) ----
#pragma unroll
        for (int mt = 0; mt < 2; ++mt) {
#pragma unroll
            for (int h = 0; h < 2; ++h) {
                int r = wm * 32 + mt * 16 + qr + (h << 3);
                float g0 = gxs[r * 14 + 2 * ly];
                float g1 = gxs[r * 14 + 2 * ly + 1];
#pragma unroll
                for (int nt = 0; nt < 4; ++nt) {
                    int c0 = wn * 32 + nt * 8 + 2 * qc;
                    float da = acc[mt][nt][2 * h];
                    float db = acc[mt][nt][2 * h + 1];
                    float va = __sinf(W0S * (da + bms[ly * 128 + c0])) +
                               __sinf(g0 * Asm[ly * 256 + c0] + g1 * Asm[ly * 256 + 128 + c0]);
                    float vb = __sinf(W0S * (db + bms[ly * 128 + c0 + 1])) +
                               __sinf(g0 * Asm[ly * 256 + c0 + 1] + g1 * Asm[ly * 256 + 129 + c0]);
                    split_store(smem, r, c0, va, vb);
                }
            }
        }

        CP_WAIT(1);        // oldest pending (Wh(ly)) complete
        __syncthreads();   // B2: x(ly+1) + Wh(ly) visible

        // ---- high GEMM (reads x(ly+1), Wh slot) ----
#pragma unroll
        for (int a = 0; a < 2; ++a)
#pragma unroll
            for (int b = 0; b < 4; ++b)
#pragma unroll
                for (int c = 0; c < 4; ++c) acc[a][b][c] = 0.0f;
        gemm_split3(sb, lane, wm, wn, woff, SOFF_WHH, SOFF_WHL, acc);

        // ---- high epilogue: buf += sin(56*(d+bh)) ----
#pragma unroll
        for (int mt = 0; mt < 2; ++mt)
#pragma unroll
            for (int nt = 0; nt < 4; ++nt) {
                int c0 = wn * 32 + nt * 8 + 2 * qc;
                float bb0 = bhs[ly * 128 + c0];
                float bb1 = bhs[ly * 128 + c0 + 1];
                buf[mt][nt][0] += __sinf(W0S * (acc[mt][nt][0] + bb0));
                buf[mt][nt][1] += __sinf(W0S * (acc[mt][nt][1] + bb1));
                buf[mt][nt][2] += __sinf(W0S * (acc[mt][nt][2] + bb0));
                buf[mt][nt][3] += __sinf(W0S * (acc[mt][nt][3] + bb1));
            }

        CP_WAIT(0);        // Wm(ly+1) complete (only remaining group)
        __syncthreads();   // B3: Wh slot free + Wm(ly+1) published

        if (ly < LVL - 1) {   // prefetch Wh(ly+1); waited at next B2
            prefetch_slot(sb, tid, ly + 1, SOFF_WHH, SOFF_WHL, g_Whh, g_Whl);
            CP_COMMIT();
        }
    }

    // output
    const float inv7 = 1.0f / 7.0f;
#pragma unroll
    for (int mt = 0; mt < 2; ++mt)
#pragma unroll
        for (int h = 0; h < 2; ++h) {
            int r = wm * 32 + mt * 16 + qr + (h << 3);
            size_t base = (size_t)(p0 + r) * 131 + 3;
#pragma unroll
            for (int nt = 0; nt < 4; ++nt) {
                int c0 = wn * 32 + nt * 8 + 2 * qc;
                out[base + c0]     = buf[mt][nt][2 * h]     * inv7;
                out[base + c0 + 1] = buf[mt][nt][2 * h + 1] * inv7;
            }
        }
}

extern "C" void kernel_launch(void* const* d_in, const int* in_sizes, int n_in,
                              void* d_out, int out_size) {
    const float* in_pos = (const float*)d_in[0];
    const float* gfeat  = (const float*)d_in[1];
    const float* ffn_A  = (const float*)d_in[2];
    const float* sigma  = (const float*)d_in[3];
    const float* W0     = (const float*)d_in[4];
    const float* b0     = (const float*)d_in[5];
    const float* W_mid  = (const float*)d_in[6];
    const float* b_mid  = (const float*)d_in[7];
    const float* W_high = (const float*)d_in[8];
    const float* b_high = (const float*)d_in[9];
    float* out = (float*)d_out;

    int N = in_sizes[0] / 3;

    prep_kernel<<<448, 256>>>(W_mid, W_high, ffn_A, sigma);

    cudaFuncSetAttribute(ffb_main, cudaFuncAttributeMaxDynamicSharedMemorySize, SMEM_TOTAL);
    ffb_main<<<N / 128, NT, SMEM_TOTAL>>>(in_pos, gfeat, W0, b0, b_mid, b_high, out);
}

// round 11
// speedup vs baseline: 2.3244x; 1.3282x over previous
#include <cuda_runtime.h>
#include <cuda_fp16.h>
#include <cstdint>

#define LVL  7
#define W0S  56.0f
#define NT   512

// SMEM byte offsets
#define SOFF_XH   0        // x hi fp16 tile, 32 KB
#define SOFF_XL   32768    // x lo fp16 tile, 32 KB
#define SOFF_WM   65536    // W_mid fp16 tile, 32 KB
#define SOFF_WH   98304    // W_high fp16 tile, 32 KB
#define SOFF_GXS  131072   // 1792 floats
#define SOFF_BMS  138240   // 896 floats
#define SOFF_BHS  141824   // 896 floats
#define SOFF_ASM  145408   // 1792 floats
#define SMEM_TOTAL 152576

// Pre-swizzled fp16 weight tiles (n-major: W[n][k]).
__device__ __align__(16) char g_Wm[LVL * 32768];
__device__ __align__(16) char g_Wh[LVL * 32768];
__device__ float g_As[LVL * 256];

// Byte offset of fp16 element (row r, col k) in a [128][128] tile.
// Row = 256B = 16 chunks of 16B; chunk index XOR (r&7) -> ldmatrix conflict-free.
__host__ __device__ __forceinline__ int swoff(int r, int k) {
    return (r << 8) + ((((k >> 3) ^ (r & 7)) & 15) << 4) + ((k & 7) << 1);
}

__global__ void prep_kernel(const float* __restrict__ Wm,
                            const float* __restrict__ Wh,
                            const float* __restrict__ A,
                            const float* __restrict__ sigma) {
    int i0 = blockIdx.x * blockDim.x + threadIdx.x;
    int stride = gridDim.x * blockDim.x;
    for (int idx = i0; idx < LVL * 16384; idx += stride) {
        int l = idx >> 14, rem = idx & 16383;
        int n = rem >> 7, k = rem & 127;
        int dst = l * 32768 + swoff(n, k);
        *(__half*)(g_Wm + dst) = __float2half(Wm[idx]);
        *(__half*)(g_Wh + dst) = __float2half(Wh[idx]);
    }
    for (int idx = i0; idx < LVL * 256; idx += stride) {
        int l = idx >> 8;
        g_As[idx] = A[idx] * (6.28318530717958647692f * sigma[l]);
    }
}

__device__ __forceinline__ uint32_t smem_u32(const void* p) {
    uint32_t a;
    asm("{ .reg .u64 t; cvta.to.shared.u64 t, %1; cvt.u32.u64 %0, t; }" : "=r"(a) : "l"(p));
    return a;
}

__device__ __forceinline__ void cp16(uint32_t dst, const void* src) {
    asm volatile("cp.async.cg.shared.global [%0], [%1], 16;" :: "r"(dst), "l"(src));
}
#define CP_COMMIT() asm volatile("cp.async.commit_group;" ::: "memory")
#define CP_WAIT(N)  asm volatile("cp.async.wait_group %0;" :: "n"(N) : "memory")

__device__ __forceinline__ void ldsm4(uint32_t* r, uint32_t addr) {
    asm volatile("ldmatrix.sync.aligned.m8n8.x4.shared.b16 {%0,%1,%2,%3}, [%4];"
                 : "=r"(r[0]), "=r"(r[1]), "=r"(r[2]), "=r"(r[3]) : "r"(addr));
}

__device__ __forceinline__ void mma16816(float* d, const uint32_t* a, const uint32_t* b) {
    asm volatile(
        "mma.sync.aligned.m16n8k16.row.col.f32.f16.f16.f32 "
        "{%0,%1,%2,%3}, {%4,%5,%6,%7}, {%8,%9}, {%0,%1,%2,%3};"
        : "+f"(d[0]), "+f"(d[1]), "+f"(d[2]), "+f"(d[3])
        : "r"(a[0]), "r"(a[1]), "r"(a[2]), "r"(a[3]), "r"(b[0]), "r"(b[1]));
}

__device__ __forceinline__ uint32_t addrA(uint32_t base, int lane, int r0, int k0) {
    int sub = lane >> 3;
    int row = r0 + (lane & 7) + ((sub & 1) << 3);
    int kk  = k0 + ((sub & 2) << 2);
    return base + (row << 8) + ((((kk >> 3) ^ (row & 7)) & 15) << 4);
}

__device__ __forceinline__ uint32_t addrB(uint32_t base, int lane, int n0, int k0) {
    int sub = lane >> 3;
    int row = n0 + (lane & 7) + ((sub & 2) << 2);
    int kk  = k0 + ((sub & 1) << 3);
    return base + (row << 8) + ((((kk >> 3) ^ (row & 7)) & 15) << 4);
}

// One 32x32 warp-tile, 2-chain fp16 split: acc += xh*W + xl*W.
__device__ __forceinline__ void gemm_split2(uint32_t sb, int lane, int wm, int wn,
                                            uint32_t offW,
                                            float acc[2][4][4]) {
#pragma unroll 1
    for (int k0 = 0; k0 < 128; k0 += 16) {
        uint32_t ah[2][4], al[2][4], b[2][4];
#pragma unroll
        for (int mt = 0; mt < 2; ++mt) {
            int r0 = wm * 32 + mt * 16;
            ldsm4(ah[mt], addrA(sb + SOFF_XH, lane, r0, k0));
            ldsm4(al[mt], addrA(sb + SOFF_XL, lane, r0, k0));
        }
#pragma unroll
        for (int nb = 0; nb < 2; ++nb) {
            int n0 = wn * 32 + nb * 16;
            ldsm4(b[nb], addrB(sb + offW, lane, n0, k0));
        }
#pragma unroll
        for (int mt = 0; mt < 2; ++mt)
#pragma unroll
            for (int nt = 0; nt < 4; ++nt) {
                const uint32_t* bp = &b[nt >> 1][(nt & 1) << 1];
                mma16816(acc[mt][nt], ah[mt], bp);
                mma16816(acc[mt][nt], al[mt], bp);
            }
    }
}

// Split v (2 adjacent cols) into fp16 hi/lo and store into x tiles.
__device__ __forceinline__ void split_store(char* smem, int r, int c0, float va, float vb) {
    __half ha = __float2half(va), hb = __float2half(vb);
    float la = va - __half2float(ha);
    float lb = vb - __half2float(hb);
    __half sla = __float2half(la), slb = __float2half(lb);
    uint32_t hi32 = ((uint32_t)__half_as_ushort(hb) << 16) | (uint32_t)__half_as_ushort(ha);
    uint32_t lo32 = ((uint32_t)__half_as_ushort(slb) << 16) | (uint32_t)__half_as_ushort(sla);
    int off = swoff(r, c0);
    *(uint32_t*)(smem + SOFF_XH + off) = hi32;
    *(uint32_t*)(smem + SOFF_XL + off) = lo32;
}

// Issue cp.asyncs for one 32 KB weight slot, layer ly. 512 threads.
__device__ __forceinline__ void prefetch_slot(uint32_t sb, int tid, int ly,
                                              uint32_t soff, const char* g) {
    const char* src = g + ly * 32768;
#pragma unroll
    for (int t = 0; t < 4; ++t) {
        int b = (tid + t * NT) * 16;
        if (b < 32768) cp16(sb + soff + b, src + b);
    }
}

__global__ void __launch_bounds__(NT, 1) ffb_main(
    const float* __restrict__ in_pos,
    const float* __restrict__ gfeat,
    const float* __restrict__ W0,
    const float* __restrict__ b0,
    const float* __restrict__ b_mid,
    const float* __restrict__ b_high,
    float* __restrict__ out) {
    extern __shared__ char smem[];
    const uint32_t sb = smem_u32(smem);
    const int tid = threadIdx.x, wid = tid >> 5, lane = tid & 31;
    const int wm = wid & 3, wn = wid >> 2;      // 4 x 4 warp grid
    const int qr = lane >> 2, qc = lane & 3;
    const int p0 = blockIdx.x << 7;

    float* gxs = (float*)(smem + SOFF_GXS);
    float* bms = (float*)(smem + SOFF_BMS);
    float* bhs = (float*)(smem + SOFF_BHS);
    float* Asm = (float*)(smem + SOFF_ASM);

    // Kick off layer-0 weight prefetch (two groups: Gm0, Gh0).
    prefetch_slot(sb, tid, 0, SOFF_WM, g_Wm);
    CP_COMMIT();
    prefetch_slot(sb, tid, 0, SOFF_WH, g_Wh);
    CP_COMMIT();

    // Stage per-CTA grid feats / biases / A (overlaps with cp.async)
    for (int idx = tid; idx < 1792; idx += NT) {
        int m = idx / 14, c = idx - m * 14;
        gxs[idx] = gfeat[(size_t)(p0 + m) * 17 + 3 + c];
        Asm[idx] = g_As[idx];
    }
    for (int idx = tid; idx < 896; idx += NT) {
        bms[idx] = b_mid[idx];
        bhs[idx] = b_high[idx];
    }

    // pos01 outputs
    if (tid < 128) {
        size_t m = p0 + tid;
        float a = in_pos[m * 3 + 0], b = in_pos[m * 3 + 1], c = in_pos[m * 3 + 2];
        out[m * 131 + 0] = (a + 1.0f) * 0.5f;
        out[m * 131 + 1] = (b + 1.0f) * 0.5f;
        out[m * 131 + 2] = (c + 1.0f) * 0.5f;
    }

    // Layer 0: x = sin(56*(pos @ W0^T + b0)) -> split tiles
    for (int p = tid; p < 8192; p += NT) {
        int r = p >> 6, n = (p & 63) << 1;
        const float* pp = in_pos + (size_t)(p0 + r) * 3;
        float x0 = pp[0], x1 = pp[1], x2 = pp[2];
        float va = __sinf(W0S * (x0 * W0[n * 3 + 0] + x1 * W0[n * 3 + 1] + x2 * W0[n * 3 + 2] + b0[n]));
        float vb = __sinf(W0S * (x0 * W0[n * 3 + 3] + x1 * W0[n * 3 + 4] + x2 * W0[n * 3 + 5] + b0[n + 1]));
        split_store(smem, r, n, va, vb);
    }

    float buf[2][4][4];
#pragma unroll
    for (int a = 0; a < 2; ++a)
#pragma unroll
        for (int b = 0; b < 4; ++b)
#pragma unroll
            for (int c = 0; c < 4; ++c) buf[a][b][c] = 0.0f;

    CP_WAIT(1);        // Wm(0) arrived (Wh(0) may still be in flight)
    __syncthreads();   // publish x(0), Wm(0), staged tables

#pragma unroll 1
    for (int ly = 0; ly < LVL; ++ly) {
        // ---- mid GEMM (reads x(ly), Wm slot) ----
        float acc[2][4][4];
#pragma unroll
        for (int a = 0; a < 2; ++a)
#pragma unroll
            for (int b = 0; b < 4; ++b)
#pragma unroll
                for (int c = 0; c < 4; ++c) acc[a][b][c] = 0.0f;
        gemm_split2(sb, lane, wm, wn, SOFF_WM, acc);
        __syncthreads();   // B1: x + Wm slot readers done

        if (ly < LVL - 1) {   // prefetch Wm(ly+1) into the now-free slot
            prefetch_slot(sb, tid, ly + 1, SOFF_WM, g_Wm);
            CP_COMMIT();
        }

        // ---- mid epilogue: x' = sin(56*(d+bm)) + sin(g.A) ----
#pragma unroll
        for (int mt = 0; mt < 2; ++mt) {
#pragma unroll
            for (int h = 0; h < 2; ++h) {
                int r = wm * 32 + mt * 16 + qr + (h << 3);
                float g0 = gxs[r * 14 + 2 * ly];
                float g1 = gxs[r * 14 + 2 * ly + 1];
#pragma unroll
                for (int nt = 0; nt < 4; ++nt) {
                    int c0 = wn * 32 + nt * 8 + 2 * qc;
                    float da = acc[mt][nt][2 * h];
                    float db = acc[mt][nt][2 * h + 1];
                    float va = __sinf(W0S * (da + bms[ly * 128 + c0])) +
                               __sinf(g0 * Asm[ly * 256 + c0] + g1 * Asm[ly * 256 + 128 + c0]);
                    float vb = __sinf(W0S * (db + bms[ly * 128 + c0 + 1])) +
                               __sinf(g0 * Asm[ly * 256 + c0 + 1] + g1 * Asm[ly * 256 + 129 + c0]);
                    split_store(smem, r, c0, va, vb);
                }
            }
        }

        CP_WAIT(1);        // oldest pending (Wh(ly)) complete
        __syncthreads();   // B2: x(ly+1) + Wh(ly) visible

        // ---- high GEMM (reads x(ly+1), Wh slot) ----
#pragma unroll
        for (int a = 0; a < 2; ++a)
#pragma unroll
            for (int b = 0; b < 4; ++b)
#pragma unroll
                for (int c = 0; c < 4; ++c) acc[a][b][c] = 0.0f;
        gemm_split2(sb, lane, wm, wn, SOFF_WH, acc);

        // ---- high epilogue: buf += sin(56*(d+bh)) ----
#pragma unroll
        for (int mt = 0; mt < 2; ++mt)
#pragma unroll
            for (int nt = 0; nt < 4; ++nt) {
                int c0 = wn * 32 + nt * 8 + 2 * qc;
                float bb0 = bhs[ly * 128 + c0];
                float bb1 = bhs[ly * 128 + c0 + 1];
                buf[mt][nt][0] += __sinf(W0S * (acc[mt][nt][0] + bb0));
                buf[mt][nt][1] += __sinf(W0S * (acc[mt][nt][1] + bb1));
                buf[mt][nt][2] += __sinf(W0S * (acc[mt][nt][2] + bb0));
                buf[mt][nt][3] += __sinf(W0S * (acc[mt][nt][3] + bb1));
            }

        CP_WAIT(0);        // Wm(ly+1) complete (only remaining group)
        __syncthreads();   // B3: Wh slot free + Wm(ly+1) published

        if (ly < LVL - 1) {   // prefetch Wh(ly+1); waited at next B2
            prefetch_slot(sb, tid, ly + 1, SOFF_WH, g_Wh);
            CP_COMMIT();
        }
    }

    // output
    const float inv7 = 1.0f / 7.0f;
#pragma unroll
    for (int mt = 0; mt < 2; ++mt)
#pragma unroll
        for (int h = 0; h < 2; ++h) {
            int r = wm * 32 + mt * 16 + qr + (h << 3);
            size_t base = (size_t)(p0 + r) * 131 + 3;
#pragma unroll
            for (int nt = 0; nt < 4; ++nt) {
                int c0 = wn * 32 + nt * 8 + 2 * qc;
                out[base + c0]     = buf[mt][nt][2 * h]     * inv7;
                out[base + c0 + 1] = buf[mt][nt][2 * h + 1] * inv7;
            }
        }
}

extern "C" void kernel_launch(void* const* d_in, const int* in_sizes, int n_in,
                              void* d_out, int out_size) {
    const float* in_pos = (const float*)d_in[0];
    const float* gfeat  = (const float*)d_in[1];
    const float* ffn_A  = (const float*)d_in[2];
    const float* sigma  = (const float*)d_in[3];
    const float* W0     = (const float*)d_in[4];
    const float* b0     = (const float*)d_in[5];
    const float* W_mid  = (const float*)d_in[6];
    const float* b_mid  = (const float*)d_in[7];
    const float* W_high = (const float*)d_in[8];
    const float* b_high = (const float*)d_in[9];
    float* out = (float*)d_out;

    int N = in_sizes[0] / 3;

    prep_kernel<<<448, 256>>>(W_mid, W_high, ffn_A, sigma);

    cudaFuncSetAttribute(ffb_main, cudaFuncAttributeMaxDynamicSharedMemorySize, SMEM_TOTAL);
    ffb_main<<<N / 128, NT, SMEM_TOTAL>>>(in_pos, gfeat, W0, b0, b_mid, b_high, out);
}

// round 12
// speedup vs baseline: 3.3785x; 1.4535x over previous
#include <cuda_runtime.h>
#include <cuda_fp16.h>
#include <cstdint>

#define LVL  7
#define W0S  56.0f
#define NT   512

// SMEM byte offsets
#define SOFF_X    0        // x fp16 tile, 32 KB
#define SOFF_WM   32768    // W_mid fp16 tile, 32 KB
#define SOFF_WH   65536    // W_high fp16 tile, 32 KB
#define SOFF_GXS  98304    // 1792 floats
#define SOFF_BMS  105472   // 896 floats
#define SOFF_BHS  109056   // 896 floats
#define SOFF_ASM  112640   // 1792 floats
#define SMEM_TOTAL 119808

// Pre-swizzled fp16 weight tiles (n-major: W[n][k]).
__device__ __align__(16) char g_Wm[LVL * 32768];
__device__ __align__(16) char g_Wh[LVL * 32768];
__device__ float g_As[LVL * 256];

// Byte offset of fp16 element (row r, col k) in a [128][128] tile.
// Row = 256B = 16 chunks of 16B; chunk index XOR (r&7) -> ldmatrix conflict-free.
__host__ __device__ __forceinline__ int swoff(int r, int k) {
    return (r << 8) + ((((k >> 3) ^ (r & 7)) & 15) << 4) + ((k & 7) << 1);
}

__global__ void prep_kernel(const float* __restrict__ Wm,
                            const float* __restrict__ Wh,
                            const float* __restrict__ A,
                            const float* __restrict__ sigma) {
    int i0 = blockIdx.x * blockDim.x + threadIdx.x;
    int stride = gridDim.x * blockDim.x;
    for (int idx = i0; idx < LVL * 16384; idx += stride) {
        int l = idx >> 14, rem = idx & 16383;
        int n = rem >> 7, k = rem & 127;
        int dst = l * 32768 + swoff(n, k);
        *(__half*)(g_Wm + dst) = __float2half(Wm[idx]);
        *(__half*)(g_Wh + dst) = __float2half(Wh[idx]);
    }
    for (int idx = i0; idx < LVL * 256; idx += stride) {
        int l = idx >> 8;
        g_As[idx] = A[idx] * (6.28318530717958647692f * sigma[l]);
    }
}

__device__ __forceinline__ uint32_t smem_u32(const void* p) {
    uint32_t a;
    asm("{ .reg .u64 t; cvta.to.shared.u64 t, %1; cvt.u32.u64 %0, t; }" : "=r"(a) : "l"(p));
    return a;
}

__device__ __forceinline__ void cp16(uint32_t dst, const void* src) {
    asm volatile("cp.async.cg.shared.global [%0], [%1], 16;" :: "r"(dst), "l"(src));
}
#define CP_COMMIT() asm volatile("cp.async.commit_group;" ::: "memory")
#define CP_WAIT(N)  asm volatile("cp.async.wait_group %0;" :: "n"(N) : "memory")

__device__ __forceinline__ void ldsm4(uint32_t* r, uint32_t addr) {
    asm volatile("ldmatrix.sync.aligned.m8n8.x4.shared.b16 {%0,%1,%2,%3}, [%4];"
                 : "=r"(r[0]), "=r"(r[1]), "=r"(r[2]), "=r"(r[3]) : "r"(addr));
}

__device__ __forceinline__ void mma16816(float* d, const uint32_t* a, const uint32_t* b) {
    asm volatile(
        "mma.sync.aligned.m16n8k16.row.col.f32.f16.f16.f32 "
        "{%0,%1,%2,%3}, {%4,%5,%6,%7}, {%8,%9}, {%0,%1,%2,%3};"
        : "+f"(d[0]), "+f"(d[1]), "+f"(d[2]), "+f"(d[3])
        : "r"(a[0]), "r"(a[1]), "r"(a[2]), "r"(a[3]), "r"(b[0]), "r"(b[1]));
}

__device__ __forceinline__ uint32_t addrA(uint32_t base, int lane, int r0, int k0) {
    int sub = lane >> 3;
    int row = r0 + (lane & 7) + ((sub & 1) << 3);
    int kk  = k0 + ((sub & 2) << 2);
    return base + (row << 8) + ((((kk >> 3) ^ (row & 7)) & 15) << 4);
}

__device__ __forceinline__ uint32_t addrB(uint32_t base, int lane, int n0, int k0) {
    int sub = lane >> 3;
    int row = n0 + (lane & 7) + ((sub & 2) << 2);
    int kk  = k0 + ((sub & 1) << 3);
    return base + (row << 8) + ((((kk >> 3) ^ (row & 7)) & 15) << 4);
}

// One 32x32 warp-tile, single-chain fp16: acc += x * W.
__device__ __forceinline__ void gemm1(uint32_t sb, int lane, int wm, int wn,
                                      uint32_t offW,
                                      float acc[2][4][4]) {
#pragma unroll 1
    for (int k0 = 0; k0 < 128; k0 += 16) {
        uint32_t a[2][4], b[2][4];
#pragma unroll
        for (int mt = 0; mt < 2; ++mt) {
            int r0 = wm * 32 + mt * 16;
            ldsm4(a[mt], addrA(sb + SOFF_X, lane, r0, k0));
        }
#pragma unroll
        for (int nb = 0; nb < 2; ++nb) {
            int n0 = wn * 32 + nb * 16;
            ldsm4(b[nb], addrB(sb + offW, lane, n0, k0));
        }
#pragma unroll
        for (int mt = 0; mt < 2; ++mt)
#pragma unroll
            for (int nt = 0; nt < 4; ++nt) {
                const uint32_t* bp = &b[nt >> 1][(nt & 1) << 1];
                mma16816(acc[mt][nt], a[mt], bp);
            }
    }
}

// Store 2 adjacent x columns as packed fp16.
__device__ __forceinline__ void x_store(char* smem, int r, int c0, float va, float vb) {
    uint32_t v = ((uint32_t)__half_as_ushort(__float2half(vb)) << 16) |
                 (uint32_t)__half_as_ushort(__float2half(va));
    *(uint32_t*)(smem + SOFF_X + swoff(r, c0)) = v;
}

// Issue cp.asyncs for one 32 KB weight slot, layer ly. 512 threads.
__device__ __forceinline__ void prefetch_slot(uint32_t sb, int tid, int ly,
                                              uint32_t soff, const char* g) {
    const char* src = g + ly * 32768;
#pragma unroll
    for (int t = 0; t < 4; ++t) {
        int b = (tid + t * NT) * 16;
        cp16(sb + soff + b, src + b);
    }
}

__global__ void __launch_bounds__(NT, 1) ffb_main(
    const float* __restrict__ in_pos,
    const float* __restrict__ gfeat,
    const float* __restrict__ W0,
    const float* __restrict__ b0,
    const float* __restrict__ b_mid,
    const float* __restrict__ b_high,
    float* __restrict__ out) {
    extern __shared__ char smem[];
    const uint32_t sb = smem_u32(smem);
    const int tid = threadIdx.x, wid = tid >> 5, lane = tid & 31;
    const int wm = wid & 3, wn = wid >> 2;      // 4 x 4 warp grid
    const int qr = lane >> 2, qc = lane & 3;
    const int p0 = blockIdx.x << 7;

    float* gxs = (float*)(smem + SOFF_GXS);
    float* bms = (float*)(smem + SOFF_BMS);
    float* bhs = (float*)(smem + SOFF_BHS);
    float* Asm = (float*)(smem + SOFF_ASM);

    // Kick off layer-0 weight prefetch (two groups: Gm0, Gh0).
    prefetch_slot(sb, tid, 0, SOFF_WM, g_Wm);
    CP_COMMIT();
    prefetch_slot(sb, tid, 0, SOFF_WH, g_Wh);
    CP_COMMIT();

    // Stage per-CTA grid feats / biases / A (overlaps with cp.async)
    for (int idx = tid; idx < 1792; idx += NT) {
        int m = idx / 14, c = idx - m * 14;
        gxs[idx] = gfeat[(size_t)(p0 + m) * 17 + 3 + c];
        Asm[idx] = g_As[idx];
    }
    for (int idx = tid; idx < 896; idx += NT) {
        bms[idx] = b_mid[idx];
        bhs[idx] = b_high[idx];
    }

    // pos01 outputs
    if (tid < 128) {
        size_t m = p0 + tid;
        float a = in_pos[m * 3 + 0], b = in_pos[m * 3 + 1], c = in_pos[m * 3 + 2];
        out[m * 131 + 0] = (a + 1.0f) * 0.5f;
        out[m * 131 + 1] = (b + 1.0f) * 0.5f;
        out[m * 131 + 2] = (c + 1.0f) * 0.5f;
    }

    // Layer 0: x = sin(56*(pos @ W0^T + b0)) -> x tile
    for (int p = tid; p < 8192; p += NT) {
        int r = p >> 6, n = (p & 63) << 1;
        const float* pp = in_pos + (size_t)(p0 + r) * 3;
        float x0 = pp[0], x1 = pp[1], x2 = pp[2];
        float va = __sinf(W0S * (x0 * W0[n * 3 + 0] + x1 * W0[n * 3 + 1] + x2 * W0[n * 3 + 2] + b0[n]));
        float vb = __sinf(W0S * (x0 * W0[n * 3 + 3] + x1 * W0[n * 3 + 4] + x2 * W0[n * 3 + 5] + b0[n + 1]));
        x_store(smem, r, n, va, vb);
    }

    float buf[2][4][4];
#pragma unroll
    for (int a = 0; a < 2; ++a)
#pragma unroll
        for (int b = 0; b < 4; ++b)
#pragma unroll
            for (int c = 0; c < 4; ++c) buf[a][b][c] = 0.0f;

    CP_WAIT(1);        // Wm(0) arrived (Wh(0) may still be in flight)
    __syncthreads();   // publish x(0), Wm(0), staged tables

#pragma unroll 1
    for (int ly = 0; ly < LVL; ++ly) {
        // ---- mid GEMM (reads x(ly), Wm slot) ----
        float acc[2][4][4];
#pragma unroll
        for (int a = 0; a < 2; ++a)
#pragma unroll
            for (int b = 0; b < 4; ++b)
#pragma unroll
                for (int c = 0; c < 4; ++c) acc[a][b][c] = 0.0f;
        gemm1(sb, lane, wm, wn, SOFF_WM, acc);
        __syncthreads();   // B1: x + Wm slot readers done

        if (ly < LVL - 1) {   // prefetch Wm(ly+1) into the now-free slot
            prefetch_slot(sb, tid, ly + 1, SOFF_WM, g_Wm);
            CP_COMMIT();
        }

        // ---- mid epilogue: x' = sin(56*(d+bm)) + sin(g.A) ----
#pragma unroll
        for (int mt = 0; mt < 2; ++mt) {
#pragma unroll
            for (int h = 0; h < 2; ++h) {
                int r = wm * 32 + mt * 16 + qr + (h << 3);
                float g0 = gxs[r * 14 + 2 * ly];
                float g1 = gxs[r * 14 + 2 * ly + 1];
#pragma unroll
                for (int nt = 0; nt < 4; ++nt) {
                    int c0 = wn * 32 + nt * 8 + 2 * qc;
                    float da = acc[mt][nt][2 * h];
                    float db = acc[mt][nt][2 * h + 1];
                    float va = __sinf(W0S * (da + bms[ly * 128 + c0])) +
                               __sinf(g0 * Asm[ly * 256 + c0] + g1 * Asm[ly * 256 + 128 + c0]);
                    float vb = __sinf(W0S * (db + bms[ly * 128 + c0 + 1])) +
                               __sinf(g0 * Asm[ly * 256 + c0 + 1] + g1 * Asm[ly * 256 + 129 + c0]);
                    x_store(smem, r, c0, va, vb);
                }
            }
        }

        CP_WAIT(1);        // oldest pending (Wh(ly)) complete
        __syncthreads();   // B2: x(ly+1) + Wh(ly) visible

        // ---- high GEMM (reads x(ly+1), Wh slot) ----
#pragma unroll
        for (int a = 0; a < 2; ++a)
#pragma unroll
            for (int b = 0; b < 4; ++b)
#pragma unroll
                for (int c = 0; c < 4; ++c) acc[a][b][c] = 0.0f;
        gemm1(sb, lane, wm, wn, SOFF_WH, acc);

        // ---- high epilogue: buf += sin(56*(d+bh)) ----
#pragma unroll
        for (int mt = 0; mt < 2; ++mt)
#pragma unroll
            for (int nt = 0; nt < 4; ++nt) {
                int c0 = wn * 32 + nt * 8 + 2 * qc;
                float bb0 = bhs[ly * 128 + c0];
                float bb1 = bhs[ly * 128 + c0 + 1];
                buf[mt][nt][0] += __sinf(W0S * (acc[mt][nt][0] + bb0));
                buf[mt][nt][1] += __sinf(W0S * (acc[mt][nt][1] + bb1));
                buf[mt][nt][2] += __sinf(W0S * (acc[mt][nt][2] + bb0));
                buf[mt][nt][3] += __sinf(W0S * (acc[mt][nt][3] + bb1));
            }

        CP_WAIT(0);        // Wm(ly+1) complete (only remaining group)
        __syncthreads();   // B3: Wh slot free + Wm(ly+1) published

        if (ly < LVL - 1) {   // prefetch Wh(ly+1); waited at next B2
            prefetch_slot(sb, tid, ly + 1, SOFF_WH, g_Wh);
            CP_COMMIT();
        }
    }

    // output
    const float inv7 = 1.0f / 7.0f;
#pragma unroll
    for (int mt = 0; mt < 2; ++mt)
#pragma unroll
        for (int h = 0; h < 2; ++h) {
            int r = wm * 32 + mt * 16 + qr + (h << 3);
            size_t base = (size_t)(p0 + r) * 131 + 3;
#pragma unroll
            for (int nt = 0; nt < 4; ++nt) {
                int c0 = wn * 32 + nt * 8 + 2 * qc;
                out[base + c0]     = buf[mt][nt][2 * h]     * inv7;
                out[base + c0 + 1] = buf[mt][nt][2 * h + 1] * inv7;
            }
        }
}

extern "C" void kernel_launch(void* const* d_in, const int* in_sizes, int n_in,
                              void* d_out, int out_size) {
    const float* in_pos = (const float*)d_in[0];
    const float* gfeat  = (const float*)d_in[1];
    const float* ffn_A  = (const float*)d_in[2];
    const float* sigma  = (const float*)d_in[3];
    const float* W0     = (const float*)d_in[4];
    const float* b0     = (const float*)d_in[5];
    const float* W_mid  = (const float*)d_in[6];
    const float* b_mid  = (const float*)d_in[7];
    const float* W_high = (const float*)d_in[8];
    const float* b_high = (const float*)d_in[9];
    float* out = (float*)d_out;

    int N = in_sizes[0] / 3;

    prep_kernel<<<448, 256>>>(W_mid, W_high, ffn_A, sigma);

    cudaFuncSetAttribute(ffb_main, cudaFuncAttributeMaxDynamicSharedMemorySize, SMEM_TOTAL);
    ffb_main<<<N / 128, NT, SMEM_TOTAL>>>(in_pos, gfeat, W0, b0, b_mid, b_high, out);
}

// round 14
// speedup vs baseline: 3.3929x; 1.0043x over previous
#include <cuda_runtime.h>
#include <cuda_fp16.h>
#include <cstdint>

#define LVL  7
#define W0S  56.0f
#define NT   512

// SMEM byte offsets — double-buffered x and weight tiles
#define SOFF_X0   0        // x buffer 0 (32 KB)
#define SOFF_X1   32768    // x buffer 1
#define SOFF_WM0  65536    // W_mid slot 0
#define SOFF_WM1  98304    // W_mid slot 1
#define SOFF_WH0  131072   // W_high slot 0
#define SOFF_WH1  163840   // W_high slot 1
#define SOFF_GXS  196608   // 1792 floats
#define SOFF_BMS  203776   // 896 floats
#define SOFF_BHS  207360   // 896 floats
#define SOFF_ASM  210944   // 1792 floats
#define SMEM_TOTAL 218112

// Pre-swizzled fp16 weight tiles (n-major: W[n][k]).
__device__ __align__(16) char g_Wm[LVL * 32768];
__device__ __align__(16) char g_Wh[LVL * 32768];
__device__ float g_As[LVL * 256];

// Byte offset of fp16 element (row r, col k) in a [128][128] tile.
// Row = 256B = 16 chunks of 16B; chunk index XOR (r&7) -> ldmatrix conflict-free.
__host__ __device__ __forceinline__ int swoff(int r, int k) {
    return (r << 8) + ((((k >> 3) ^ (r & 7)) & 15) << 4) + ((k & 7) << 1);
}

__global__ void prep_kernel(const float* __restrict__ Wm,
                            const float* __restrict__ Wh,
                            const float* __restrict__ A,
                            const float* __restrict__ sigma) {
    int i0 = blockIdx.x * blockDim.x + threadIdx.x;
    int stride = gridDim.x * blockDim.x;
    for (int idx = i0; idx < LVL * 16384; idx += stride) {
        int l = idx >> 14, rem = idx & 16383;
        int n = rem >> 7, k = rem & 127;
        int dst = l * 32768 + swoff(n, k);
        *(__half*)(g_Wm + dst) = __float2half(Wm[idx]);
        *(__half*)(g_Wh + dst) = __float2half(Wh[idx]);
    }
    for (int idx = i0; idx < LVL * 256; idx += stride) {
        int l = idx >> 8;
        g_As[idx] = A[idx] * (6.28318530717958647692f * sigma[l]);
    }
}

__device__ __forceinline__ uint32_t smem_u32(const void* p) {
    uint32_t a;
    asm("{ .reg .u64 t; cvta.to.shared.u64 t, %1; cvt.u32.u64 %0, t; }" : "=r"(a) : "l"(p));
    return a;
}

__device__ __forceinline__ void cp16(uint32_t dst, const void* src) {
    asm volatile("cp.async.cg.shared.global [%0], [%1], 16;" :: "r"(dst), "l"(src));
}
#define CP_COMMIT() asm volatile("cp.async.commit_group;" ::: "memory")
#define CP_WAIT(N)  asm volatile("cp.async.wait_group %0;" :: "n"(N) : "memory")

__device__ __forceinline__ void ldsm4(uint32_t* r, uint32_t addr) {
    asm volatile("ldmatrix.sync.aligned.m8n8.x4.shared.b16 {%0,%1,%2,%3}, [%4];"
                 : "=r"(r[0]), "=r"(r[1]), "=r"(r[2]), "=r"(r[3]) : "r"(addr));
}

__device__ __forceinline__ void mma16816(float* d, const uint32_t* a, const uint32_t* b) {
    asm volatile(
        "mma.sync.aligned.m16n8k16.row.col.f32.f16.f16.f32 "
        "{%0,%1,%2,%3}, {%4,%5,%6,%7}, {%8,%9}, {%0,%1,%2,%3};"
        : "+f"(d[0]), "+f"(d[1]), "+f"(d[2]), "+f"(d[3])
        : "r"(a[0]), "r"(a[1]), "r"(a[2]), "r"(a[3]), "r"(b[0]), "r"(b[1]));
}

__device__ __forceinline__ uint32_t addrA(uint32_t base, int lane, int r0, int k0) {
    int sub = lane >> 3;
    int row = r0 + (lane & 7) + ((sub & 1) << 3);
    int kk  = k0 + ((sub & 2) << 2);
    return base + (row << 8) + ((((kk >> 3) ^ (row & 7)) & 15) << 4);
}

__device__ __forceinline__ uint32_t addrB(uint32_t base, int lane, int n0, int k0) {
    int sub = lane >> 3;
    int row = n0 + (lane & 7) + ((sub & 2) << 2);
    int kk  = k0 + ((sub & 1) << 3);
    return base + (row << 8) + ((((kk >> 3) ^ (row & 7)) & 15) << 4);
}

// One 32x32 warp-tile, single-chain fp16: acc += x * W.
__device__ __forceinline__ void gemm1(uint32_t sb, int lane, int wm, int wn,
                                      uint32_t offX, uint32_t offW,
                                      float acc[2][4][4]) {
#pragma unroll 1
    for (int k0 = 0; k0 < 128; k0 += 16) {
        uint32_t a[2][4], b[2][4];
#pragma unroll
        for (int mt = 0; mt < 2; ++mt) {
            int r0 = wm * 32 + mt * 16;
            ldsm4(a[mt], addrA(sb + offX, lane, r0, k0));
        }
#pragma unroll
        for (int nb = 0; nb < 2; ++nb) {
            int n0 = wn * 32 + nb * 16;
            ldsm4(b[nb], addrB(sb + offW, lane, n0, k0));
        }
#pragma unroll
        for (int mt = 0; mt < 2; ++mt)
#pragma unroll
            for (int nt = 0; nt < 4; ++nt) {
                const uint32_t* bp = &b[nt >> 1][(nt & 1) << 1];
                mma16816(acc[mt][nt], a[mt], bp);
            }
    }
}

// Store 2 adjacent x columns as packed fp16 into the given x buffer.
__device__ __forceinline__ void x_store(char* smem, uint32_t xoff, int r, int c0,
                                        float va, float vb) {
    uint32_t v = ((uint32_t)__half_as_ushort(__float2half(vb)) << 16) |
                 (uint32_t)__half_as_ushort(__float2half(va));
    *(uint32_t*)(smem + xoff + swoff(r, c0)) = v;
}

// Issue cp.asyncs for one 32 KB weight slot, layer ly. 512 threads.
__device__ __forceinline__ void prefetch_slot(uint32_t sb, int tid, int ly,
                                              uint32_t soff, const char* g) {
    const char* src = g + ly * 32768;
#pragma unroll
    for (int t = 0; t < 4; ++t) {
        int b = (tid + t * NT) * 16;
        cp16(sb + soff + b, src + b);
    }
}

__global__ void __launch_bounds__(NT, 1) ffb_main(
    const float* __restrict__ in_pos,
    const float* __restrict__ gfeat,
    const float* __restrict__ W0,
    const float* __restrict__ b0,
    const float* __restrict__ b_mid,
    const float* __restrict__ b_high,
    float* __restrict__ out) {
    extern __shared__ char smem[];
    const uint32_t sb = smem_u32(smem);
    const int tid = threadIdx.x, wid = tid >> 5, lane = tid & 31;
    const int wm = wid & 3, wn = wid >> 2;      // 4 x 4 warp grid
    const int qr = lane >> 2, qc = lane & 3;
    const int p0 = blockIdx.x << 7;

    float* gxs = (float*)(smem + SOFF_GXS);
    float* bms = (float*)(smem + SOFF_BMS);
    float* bhs = (float*)(smem + SOFF_BHS);
    float* Asm = (float*)(smem + SOFF_ASM);

    // Kick off prefetch: Wm(0)->WM0, Wh(0)->WH0, Wm(1)->WM1.
    prefetch_slot(sb, tid, 0, SOFF_WM0, g_Wm);
    prefetch_slot(sb, tid, 0, SOFF_WH0, g_Wh);
    if (LVL > 1) prefetch_slot(sb, tid, 1, SOFF_WM1, g_Wm);
    CP_COMMIT();

    // Stage per-CTA grid feats / biases / A (overlaps with cp.async)
    for (int idx = tid; idx < 1792; idx += NT) {
        int m = idx / 14, c = idx - m * 14;
        gxs[idx] = gfeat[(size_t)(p0 + m) * 17 + 3 + c];
        Asm[idx] = g_As[idx];
    }
    for (int idx = tid; idx < 896; idx += NT) {
        bms[idx] = b_mid[idx];
        bhs[idx] = b_high[idx];
    }

    // pos01 outputs
    if (tid < 128) {
        size_t m = p0 + tid;
        float a = in_pos[m * 3 + 0], b = in_pos[m * 3 + 1], c = in_pos[m * 3 + 2];
        out[m * 131 + 0] = (a + 1.0f) * 0.5f;
        out[m * 131 + 1] = (b + 1.0f) * 0.5f;
        out[m * 131 + 2] = (c + 1.0f) * 0.5f;
    }

    // Layer 0: x(0) = sin(56*(pos @ W0^T + b0)) -> x buffer 0
    for (int p = tid; p < 8192; p += NT) {
        int r = p >> 6, n = (p & 63) << 1;
        const float* pp = in_pos + (size_t)(p0 + r) * 3;
        float x0 = pp[0], x1 = pp[1], x2 = pp[2];
        float va = __sinf(W0S * (x0 * W0[n * 3 + 0] + x1 * W0[n * 3 + 1] + x2 * W0[n * 3 + 2] + b0[n]));
        float vb = __sinf(W0S * (x0 * W0[n * 3 + 3] + x1 * W0[n * 3 + 4] + x2 * W0[n * 3 + 5] + b0[n + 1]));
        x_store(smem, SOFF_X0, r, n, va, vb);
    }

    float buf[2][4][4];
#pragma unroll
    for (int a = 0; a < 2; ++a)
#pragma unroll
        for (int b = 0; b < 4; ++b)
#pragma unroll
            for (int c = 0; c < 4; ++c) buf[a][b][c] = 0.0f;

    CP_WAIT(0);        // Wm(0), Wh(0), Wm(1) arrived
    __syncthreads();   // publish x(0), weights, tables

#pragma unroll 1
    for (int ly = 0; ly < LVL; ++ly) {
        const uint32_t xcur = SOFF_X0  + (uint32_t)((ly & 1) << 15);
        const uint32_t xnxt = SOFF_X0  + (uint32_t)(((ly + 1) & 1) << 15);
        const uint32_t wmS  = SOFF_WM0 + (uint32_t)((ly & 1) << 15);
        const uint32_t whS  = SOFF_WH0 + (uint32_t)((ly & 1) << 15);

        // ---- mid GEMM (reads x(ly) in xcur, Wm slot ly%2) ----
        float acc[2][4][4];
#pragma unroll
        for (int a = 0; a < 2; ++a)
#pragma unroll
            for (int b = 0; b < 4; ++b)
#pragma unroll
                for (int c = 0; c < 4; ++c) acc[a][b][c] = 0.0f;
        gemm1(sb, lane, wm, wn, xcur, wmS, acc);

        // ---- mid epilogue -> x(ly+1) into xnxt (other buffer; no fence needed) ----
#pragma unroll
        for (int mt = 0; mt < 2; ++mt) {
#pragma unroll
            for (int h = 0; h < 2; ++h) {
                int r = wm * 32 + mt * 16 + qr + (h << 3);
                float g0 = gxs[r * 14 + 2 * ly];
                float g1 = gxs[r * 14 + 2 * ly + 1];
#pragma unroll
                for (int nt = 0; nt < 4; ++nt) {
                    int c0 = wn * 32 + nt * 8 + 2 * qc;
                    float da = acc[mt][nt][2 * h];
                    float db = acc[mt][nt][2 * h + 1];
                    float va = __sinf(W0S * (da + bms[ly * 128 + c0])) +
                               __sinf(g0 * Asm[ly * 256 + c0] + g1 * Asm[ly * 256 + 128 + c0]);
                    float vb = __sinf(W0S * (db + bms[ly * 128 + c0 + 1])) +
                               __sinf(g0 * Asm[ly * 256 + c0 + 1] + g1 * Asm[ly * 256 + 129 + c0]);
                    x_store(smem, xnxt, r, c0, va, vb);
                }
            }
        }

        // ---- THE one barrier: publish x(ly+1) + pending weight prefetches ----
        CP_WAIT(0);
        __syncthreads();

        // Prefetch next weights into slots whose readers are sealed by this sync:
        //   Wh(ly+1) -> Wh[(ly+1)%2]  (old Wh(ly-1) readers done at SYNC(ly-1..ly))
        //   Wm(ly+2) -> Wm[ly%2]      (Wm(ly) readers done above)
        if (ly + 1 < LVL) {
            prefetch_slot(sb, tid, ly + 1, SOFF_WH0 + (uint32_t)(((ly + 1) & 1) << 15), g_Wh);
            if (ly + 2 < LVL)
                prefetch_slot(sb, tid, ly + 2, SOFF_WM0 + (uint32_t)((ly & 1) << 15), g_Wm);
            CP_COMMIT();
        }

        // ---- high GEMM (reads x(ly+1) in xnxt, Wh slot ly%2) ----
#pragma unroll
        for (int a = 0; a < 2; ++a)
#pragma unroll
            for (int b = 0; b < 4; ++b)
#pragma unroll
                for (int c = 0; c < 4; ++c) acc[a][b][c] = 0.0f;
        gemm1(sb, lane, wm, wn, xnxt, whS, acc);

        // ---- high epilogue: buf += sin(56*(d+bh)) (registers; fence-free) ----
#pragma unroll
        for (int mt = 0; mt < 2; ++mt)
#pragma unroll
            for (int nt = 0; nt < 4; ++nt) {
                int c0 = wn * 32 + nt * 8 + 2 * qc;
                float bb0 = bhs[ly * 128 + c0];
                float bb1 = bhs[ly * 128 + c0 + 1];
                buf[mt][nt][0] += __sinf(W0S * (acc[mt][nt][0] + bb0));
                buf[mt][nt][1] += __sinf(W0S * (acc[mt][nt][1] + bb1));
                buf[mt][nt][2] += __sinf(W0S * (acc[mt][nt][2] + bb0));
                buf[mt][nt][3] += __sinf(W0S * (acc[mt][nt][3] + bb1));
            }
    }

    // output
    const float inv7 = 1.0f / 7.0f;
#pragma unroll
    for (int mt = 0; mt < 2; ++mt)
#pragma unroll
        for (int h = 0; h < 2; ++h) {
            int r = wm * 32 + mt * 16 + qr + (h << 3);
            size_t base = (size_t)(p0 + r) * 131 + 3;
#pragma unroll
            for (int nt = 0; nt < 4; ++nt) {
                int c0 = wn * 32 + nt * 8 + 2 * qc;
                out[base + c0]     = buf[mt][nt][2 * h]     * inv7;
                out[base + c0 + 1] = buf[mt][nt][2 * h + 1] * inv7;
            }
        }
}

extern "C" void kernel_launch(void* const* d_in, const int* in_sizes, int n_in,
                              void* d_out, int out_size) {
    const float* in_pos = (const float*)d_in[0];
    const float* gfeat  = (const float*)d_in[1];
    const float* ffn_A  = (const float*)d_in[2];
    const float* sigma  = (const float*)d_in[3];
    const float* W0     = (const float*)d_in[4];
    const float* b0     = (const float*)d_in[5];
    const float* W_mid  = (const float*)d_in[6];
    const float* b_mid  = (const float*)d_in[7];
    const float* W_high = (const float*)d_in[8];
    const float* b_high = (const float*)d_in[9];
    float* out = (float*)d_out;

    int N = in_sizes[0] / 3;

    prep_kernel<<<448, 256>>>(W_mid, W_high, ffn_A, sigma);

    cudaFuncSetAttribute(ffb_main, cudaFuncAttributeMaxDynamicSharedMemorySize, SMEM_TOTAL);
    ffb_main<<<N / 128, NT, SMEM_TOTAL>>>(in_pos, gfeat, W0, b0, b_mid, b_high, out);
}

// round 16
// speedup vs baseline: 3.5530x; 1.0472x over previous
#include <cuda_runtime.h>
#include <cuda_fp16.h>
#include <cstdint>

#define LVL  7
#define W0S  56.0f
#define NT   256    // threads per CTA (8 warps), 2 CTAs/SM
#define MP   64     // points per CTA

// SMEM byte offsets
#define SOFF_X    0        // x fp16 tile 64x128, 16 KB
#define SOFF_WM   16384    // W_mid fp16 tile, 32 KB
#define SOFF_WH   49152    // W_high fp16 tile, 32 KB
#define SOFF_GXS  81920    // 896 floats
#define SOFF_BMS  85504    // 896 floats
#define SOFF_BHS  89088    // 896 floats
#define SOFF_ASM  92672    // 1792 floats
#define SMEM_TOTAL 99840

// Pre-swizzled fp16 weight tiles (n-major: W[n][k]).
__device__ __align__(16) char g_Wm[LVL * 32768];
__device__ __align__(16) char g_Wh[LVL * 32768];
__device__ float g_As[LVL * 256];

// Byte offset of fp16 element (row r, col k); 256B rows, XOR-chunk swizzle.
__host__ __device__ __forceinline__ int swoff(int r, int k) {
    return (r << 8) + ((((k >> 3) ^ (r & 7)) & 15) << 4) + ((k & 7) << 1);
}

__global__ void prep_kernel(const float* __restrict__ Wm,
                            const float* __restrict__ Wh,
                            const float* __restrict__ A,
                            const float* __restrict__ sigma) {
    int i0 = blockIdx.x * blockDim.x + threadIdx.x;
    int stride = gridDim.x * blockDim.x;
    for (int idx = i0; idx < LVL * 16384; idx += stride) {
        int l = idx >> 14, rem = idx & 16383;
        int n = rem >> 7, k = rem & 127;
        int dst = l * 32768 + swoff(n, k);
        *(__half*)(g_Wm + dst) = __float2half(Wm[idx]);
        *(__half*)(g_Wh + dst) = __float2half(Wh[idx]);
    }
    for (int idx = i0; idx < LVL * 256; idx += stride) {
        int l = idx >> 8;
        g_As[idx] = A[idx] * (6.28318530717958647692f * sigma[l]);
    }
}

__device__ __forceinline__ uint32_t smem_u32(const void* p) {
    uint32_t a;
    asm("{ .reg .u64 t; cvta.to.shared.u64 t, %1; cvt.u32.u64 %0, t; }" : "=r"(a) : "l"(p));
    return a;
}

__device__ __forceinline__ void cp16(uint32_t dst, const void* src) {
    asm volatile("cp.async.cg.shared.global [%0], [%1], 16;" :: "r"(dst), "l"(src));
}
#define CP_COMMIT() asm volatile("cp.async.commit_group;" ::: "memory")
#define CP_WAIT(N)  asm volatile("cp.async.wait_group %0;" :: "n"(N) : "memory")

__device__ __forceinline__ void ldsm4(uint32_t* r, uint32_t addr) {
    asm volatile("ldmatrix.sync.aligned.m8n8.x4.shared.b16 {%0,%1,%2,%3}, [%4];"
                 : "=r"(r[0]), "=r"(r[1]), "=r"(r[2]), "=r"(r[3]) : "r"(addr));
}

__device__ __forceinline__ void mma16816(float* d, const uint32_t* a, const uint32_t* b) {
    asm volatile(
        "mma.sync.aligned.m16n8k16.row.col.f32.f16.f16.f32 "
        "{%0,%1,%2,%3}, {%4,%5,%6,%7}, {%8,%9}, {%0,%1,%2,%3};"
        : "+f"(d[0]), "+f"(d[1]), "+f"(d[2]), "+f"(d[3])
        : "r"(a[0]), "r"(a[1]), "r"(a[2]), "r"(a[3]), "r"(b[0]), "r"(b[1]));
}

__device__ __forceinline__ uint32_t addrA(uint32_t base, int lane, int r0, int k0) {
    int sub = lane >> 3;
    int row = r0 + (lane & 7) + ((sub & 1) << 3);
    int kk  = k0 + ((sub & 2) << 2);
    return base + (row << 8) + ((((kk >> 3) ^ (row & 7)) & 15) << 4);
}

__device__ __forceinline__ uint32_t addrB(uint32_t base, int lane, int n0, int k0) {
    int sub = lane >> 3;
    int row = n0 + (lane & 7) + ((sub & 2) << 2);
    int kk  = k0 + ((sub & 1) << 3);
    return base + (row << 8) + ((((kk >> 3) ^ (row & 7)) & 15) << 4);
}

// One 32x32 warp-tile, single-chain fp16: acc += x * W.
__device__ __forceinline__ void gemm1(uint32_t sb, int lane, int wm, int wn,
                                      uint32_t offW,
                                      float acc[2][4][4]) {
#pragma unroll 1
    for (int k0 = 0; k0 < 128; k0 += 16) {
        uint32_t a[2][4], b[2][4];
#pragma unroll
        for (int mt = 0; mt < 2; ++mt) {
            int r0 = wm * 32 + mt * 16;
            ldsm4(a[mt], addrA(sb + SOFF_X, lane, r0, k0));
        }
#pragma unroll
        for (int nb = 0; nb < 2; ++nb) {
            int n0 = wn * 32 + nb * 16;
            ldsm4(b[nb], addrB(sb + offW, lane, n0, k0));
        }
#pragma unroll
        for (int mt = 0; mt < 2; ++mt)
#pragma unroll
            for (int nt = 0; nt < 4; ++nt) {
                const uint32_t* bp = &b[nt >> 1][(nt & 1) << 1];
                mma16816(acc[mt][nt], a[mt], bp);
            }
    }
}

// Store 2 adjacent x columns as packed fp16.
__device__ __forceinline__ void x_store(char* smem, int r, int c0, float va, float vb) {
    uint32_t v = ((uint32_t)__half_as_ushort(__float2half(vb)) << 16) |
                 (uint32_t)__half_as_ushort(__float2half(va));
    *(uint32_t*)(smem + SOFF_X + swoff(r, c0)) = v;
}

// Issue cp.asyncs for one 32 KB weight slot, layer ly. 256 threads.
__device__ __forceinline__ void prefetch_slot(uint32_t sb, int tid, int ly,
                                              uint32_t soff, const char* g) {
    const char* src = g + ly * 32768;
#pragma unroll
    for (int t = 0; t < 8; ++t) {
        int b = (tid + t * NT) * 16;
        cp16(sb + soff + b, src + b);
    }
}

__global__ void __launch_bounds__(NT, 2) ffb_main(
    const float* __restrict__ in_pos,
    const float* __restrict__ gfeat,
    const float* __restrict__ W0,
    const float* __restrict__ b0,
    const float* __restrict__ b_mid,
    const float* __restrict__ b_high,
    float* __restrict__ out) {
    extern __shared__ char smem[];
    const uint32_t sb = smem_u32(smem);
    const int tid = threadIdx.x, wid = tid >> 5, lane = tid & 31;
    const int wm = wid & 1, wn = wid >> 1;      // 2 x 4 warp grid (64M x 128N)
    const int qr = lane >> 2, qc = lane & 3;
    const int p0 = blockIdx.x << 6;

    float* gxs = (float*)(smem + SOFF_GXS);
    float* bms = (float*)(smem + SOFF_BMS);
    float* bhs = (float*)(smem + SOFF_BHS);
    float* Asm = (float*)(smem + SOFF_ASM);

    // Kick off layer-0 weight prefetch (two groups: Gm0, Gh0).
    prefetch_slot(sb, tid, 0, SOFF_WM, g_Wm);
    CP_COMMIT();
    prefetch_slot(sb, tid, 0, SOFF_WH, g_Wh);
    CP_COMMIT();

    // Stage per-CTA grid feats / biases / A (overlaps with cp.async)
    for (int idx = tid; idx < 896; idx += NT) {
        int m = idx / 14, c = idx - m * 14;
        gxs[idx] = gfeat[(size_t)(p0 + m) * 17 + 3 + c];
        bms[idx] = b_mid[idx];
        bhs[idx] = b_high[idx];
    }
    for (int idx = tid; idx < 1792; idx += NT) Asm[idx] = g_As[idx];

    // pos01 outputs
    if (tid < MP) {
        size_t m = p0 + tid;
        float a = in_pos[m * 3 + 0], b = in_pos[m * 3 + 1], c = in_pos[m * 3 + 2];
        out[m * 131 + 0] = (a + 1.0f) * 0.5f;
        out[m * 131 + 1] = (b + 1.0f) * 0.5f;
        out[m * 131 + 2] = (c + 1.0f) * 0.5f;
    }

    // Layer 0: x = sin(56*(pos @ W0^T + b0)) -> x tile (64 rows)
    for (int p = tid; p < MP * 64; p += NT) {
        int r = p >> 6, n = (p & 63) << 1;
        const float* pp = in_pos + (size_t)(p0 + r) * 3;
        float x0 = pp[0], x1 = pp[1], x2 = pp[2];
        float va = __sinf(W0S * (x0 * W0[n * 3 + 0] + x1 * W0[n * 3 + 1] + x2 * W0[n * 3 + 2] + b0[n]));
        float vb = __sinf(W0S * (x0 * W0[n * 3 + 3] + x1 * W0[n * 3 + 4] + x2 * W0[n * 3 + 5] + b0[n + 1]));
        x_store(smem, r, n, va, vb);
    }

    float buf[2][4][4];
#pragma unroll
    for (int a = 0; a < 2; ++a)
#pragma unroll
        for (int b = 0; b < 4; ++b)
#pragma unroll
            for (int c = 0; c < 4; ++c) buf[a][b][c] = 0.0f;

    CP_WAIT(1);        // Wm(0) arrived (Wh(0) may still be in flight)
    __syncthreads();   // publish x(0), Wm(0), staged tables

#pragma unroll 1
    for (int ly = 0; ly < LVL; ++ly) {
        // ---- mid GEMM (reads x(ly), Wm slot) ----
        float acc[2][4][4];
#pragma unroll
        for (int a = 0; a < 2; ++a)
#pragma unroll
            for (int b = 0; b < 4; ++b)
#pragma unroll
                for (int c = 0; c < 4; ++c) acc[a][b][c] = 0.0f;
        gemm1(sb, lane, wm, wn, SOFF_WM, acc);
        __syncthreads();   // B1: x + Wm slot readers done

        if (ly < LVL - 1) {   // prefetch Wm(ly+1) into the now-free slot
            prefetch_slot(sb, tid, ly + 1, SOFF_WM, g_Wm);
            CP_COMMIT();
        }

        // ---- mid epilogue: x' = sin(56*(d+bm)) + sin(g.A) ----
#pragma unroll
        for (int mt = 0; mt < 2; ++mt) {
#pragma unroll
            for (int h = 0; h < 2; ++h) {
                int r = wm * 32 + mt * 16 + qr + (h << 3);
                float g0 = gxs[r * 14 + 2 * ly];
                float g1 = gxs[r * 14 + 2 * ly + 1];
#pragma unroll
                for (int nt = 0; nt < 4; ++nt) {
                    int c0 = wn * 32 + nt * 8 + 2 * qc;
                    float da = acc[mt][nt][2 * h];
                    float db = acc[mt][nt][2 * h + 1];
                    float va = __sinf(W0S * (da + bms[ly * 128 + c0])) +
                               __sinf(g0 * Asm[ly * 256 + c0] + g1 * Asm[ly * 256 + 128 + c0]);
                    float vb = __sinf(W0S * (db + bms[ly * 128 + c0 + 1])) +
                               __sinf(g0 * Asm[ly * 256 + c0 + 1] + g1 * Asm[ly * 256 + 129 + c0]);
                    x_store(smem, r, c0, va, vb);
                }
            }
        }

        CP_WAIT(1);        // oldest pending (Wh(ly)) complete
        __syncthreads();   // B2: x(ly+1) + Wh(ly) visible

        // ---- high GEMM (reads x(ly+1), Wh slot) ----
#pragma unroll
        for (int a = 0; a < 2; ++a)
#pragma unroll
            for (int b = 0; b < 4; ++b)
#pragma unroll
                for (int c = 0; c < 4; ++c) acc[a][b][c] = 0.0f;
        gemm1(sb, lane, wm, wn, SOFF_WH, acc);

        // ---- high epilogue: buf += sin(56*(d+bh)) ----
#pragma unroll
        for (int mt = 0; mt < 2; ++mt)
#pragma unroll
            for (int nt = 0; nt < 4; ++nt) {
                int c0 = wn * 32 + nt * 8 + 2 * qc;
                float bb0 = bhs[ly * 128 + c0];
                float bb1 = bhs[ly * 128 + c0 + 1];
                buf[mt][nt][0] += __sinf(W0S * (acc[mt][nt][0] + bb0));
                buf[mt][nt][1] += __sinf(W0S * (acc[mt][nt][1] + bb1));
                buf[mt][nt][2] += __sinf(W0S * (acc[mt][nt][2] + bb0));
                buf[mt][nt][3] += __sinf(W0S * (acc[mt][nt][3] + bb1));
            }

        CP_WAIT(0);        // Wm(ly+1) complete (only remaining group)
        __syncthreads();   // B3: Wh slot free + Wm(ly+1) published

        if (ly < LVL - 1) {   // prefetch Wh(ly+1); waited at next B2
            prefetch_slot(sb, tid, ly + 1, SOFF_WH, g_Wh);
            CP_COMMIT();
        }
    }

    // output
    const float inv7 = 1.0f / 7.0f;
#pragma unroll
    for (int mt = 0; mt < 2; ++mt)
#pragma unroll
        for (int h = 0; h < 2; ++h) {
            int r = wm * 32 + mt * 16 + qr + (h << 3);
            size_t base = (size_t)(p0 + r) * 131 + 3;
#pragma unroll
            for (int nt = 0; nt < 4; ++nt) {
                int c0 = wn * 32 + nt * 8 + 2 * qc;
                out[base + c0]     = buf[mt][nt][2 * h]     * inv7;
                out[base + c0 + 1] = buf[mt][nt][2 * h + 1] * inv7;
            }
        }
}

extern "C" void kernel_launch(void* const* d_in, const int* in_sizes, int n_in,
                              void* d_out, int out_size) {
    const float* in_pos = (const float*)d_in[0];
    const float* gfeat  = (const float*)d_in[1];
    const float* ffn_A  = (const float*)d_in[2];
    const float* sigma  = (const float*)d_in[3];
    const float* W0     = (const float*)d_in[4];
    const float* b0     = (const float*)d_in[5];
    const float* W_mid  = (const float*)d_in[6];
    const float* b_mid  = (const float*)d_in[7];
    const float* W_high = (const float*)d_in[8];
    const float* b_high = (const float*)d_in[9];
    float* out = (float*)d_out;

    int N = in_sizes[0] / 3;

    prep_kernel<<<448, 256>>>(W_mid, W_high, ffn_A, sigma);

    cudaFuncSetAttribute(ffb_main, cudaFuncAttributeMaxDynamicSharedMemorySize, SMEM_TOTAL);
    ffb_main<<<N / MP, NT, SMEM_TOTAL>>>(in_pos, gfeat, W0, b0, b_mid, b_high, out);
}